// round 2
// baseline (speedup 1.0000x reference)
#include <cuda_runtime.h>

// ---------------------------------------------------------------------------
// RNNSent: 2-layer LSTM (T=300 steps after the .view trick), B=1024, NHID=256
// Layer0 in-dim 25 (padded to 32), Layer1 in-dim 256.
// Outputs: decoded.T [2,1024] ++ h [2,1024,256] ++ c [2,1024,256]  (fp32)
// ---------------------------------------------------------------------------

#define Bsz   1024
#define Tst   300
#define NH    256
#define NG    1024        // 4*NH gate rows
#define KX    32          // padded layer0 input dim (25 -> 32)
#define GSIZE 8           // CTAs per batch-group (hidden split 256/32)
#define NGRP  16          // batch groups (1024/64)
#define NCTA  128

// -------------------- device scratch (static, no allocations) --------------
__device__ float g_X[(size_t)Tst * Bsz * KX];              // [t][b][kx] padded emb
// rows: [0,32)=Wih0T, [32,288)=Whh0T, [288,544)=Wih1T, [544,800)=Whh1T
// each row has 1024 cols permuted so CTA hi's 128 gate-cols are contiguous:
// col' = hi*128 + g*32 + j  for gate row r = g*256 + hi*32 + j
__device__ float g_WT[(size_t)(KX + 3 * NH) * NG];
__device__ float g_bias[2 * NG];                            // permuted b_ih+b_hh
__device__ float g_H0[2 * Bsz * NH];                        // double-buffered h, layer0
__device__ float g_H1[2 * Bsz * NH];                        // layer1
__device__ unsigned g_bar_count[NGRP];
__device__ unsigned g_bar_gen[NGRP];

// -------------------- kernel 1: embedding gather + pad ---------------------
__global__ void gather_emb_kernel(const int* __restrict__ input,
                                  const float* __restrict__ emb) {
    long idx = (long)blockIdx.x * blockDim.x + threadIdx.x;
    long total = (long)Tst * Bsz * KX;
    if (idx >= total) return;
    int k = (int)(idx & (KX - 1));
    long tb = idx >> 5;
    int b = (int)(tb & (Bsz - 1));
    int t = (int)(tb >> 10);
    float v = 0.f;
    if (k < 25) {
        // x[t][b][k] = flat E index t*25600 + b*25 + k over emb[25][1024][300]
        long flat = (long)t * (Bsz * 25) + b * 25 + k;
        int s  = (int)(flat / (Bsz * 300));
        int rr = (int)(flat % (Bsz * 300));
        int bb = rr / 300;
        int e  = rr % 300;
        int tok = input[bb * 25 + s];
        v = emb[(long)tok * 300 + e];
    }
    g_X[idx] = v;
}

// -------------------- kernel 2: weight transpose + permute -----------------
__global__ void prep_weights_kernel(
    const float* __restrict__ Wih0, const float* __restrict__ Whh0,
    const float* __restrict__ bih0, const float* __restrict__ bhh0,
    const float* __restrict__ Wih1, const float* __restrict__ Whh1,
    const float* __restrict__ bih1, const float* __restrict__ bhh1) {
    int idx = blockIdx.x * blockDim.x + threadIdx.x;
    const int total = (KX + 3 * NH) * NG;   // 819200
    if (idx < total) {
        int row  = idx >> 10;
        int colp = idx & 1023;
        int hi = colp >> 7, g = (colp >> 5) & 3, j = colp & 31;
        int r = g * 256 + hi * 32 + j;      // original gate row
        float v;
        if (row < KX)               { int k = row;               v = (k < 25) ? Wih0[r * 25 + k] : 0.f; }
        else if (row < KX + NH)     { int k = row - KX;          v = Whh0[r * 256 + k]; }
        else if (row < KX + 2 * NH) { int k = row - (KX + NH);   v = Wih1[r * 256 + k]; }
        else                        { int k = row - (KX + 2*NH); v = Whh1[r * 256 + k]; }
        g_WT[idx] = v;
    } else if (idx < total + 2 * NG) {
        int i2 = idx - total;
        int l = i2 >> 10, colp = i2 & 1023;
        int hi = colp >> 7, g = (colp >> 5) & 3, j = colp & 31;
        int r = g * 256 + hi * 32 + j;
        g_bias[i2] = (l == 0) ? (bih0[r] + bhh0[r]) : (bih1[r] + bhh1[r]);
    }
}

// -------------------- group barrier (8 co-resident CTAs) -------------------
__device__ __forceinline__ void group_barrier(int grp) {
    __syncthreads();
    if (threadIdx.x == 0) {
        __threadfence();   // release: make this CTA's h writes visible (gpu scope)
        volatile unsigned* genp = &g_bar_gen[grp];
        unsigned gen = *genp;
        unsigned old = atomicAdd(&g_bar_count[grp], 1u);
        if (old == GSIZE - 1) {
            ((volatile unsigned*)&g_bar_count[grp])[0] = 0u;
            __threadfence();
            atomicExch(&g_bar_gen[grp], gen + 1u);
        } else {
            while (*genp == gen) { __nanosleep(64); }
        }
        __threadfence();   // acquire: L1 invalidate before reading peers' h
    }
    __syncthreads();
}

// -------------------- fp32 register-tiled GEMM fragment --------------------
// CTA computes G[64 batch, 128 gatecols] accumulating over K.
// Thread (ty in [0,8), tx in [0,32)): 8 batch rows (b0=ty*8) x 4 gates of j=tx.
__device__ __forceinline__ void load_frag(const float* __restrict__ Ag, int lda,
                                          const float* __restrict__ Wrow, int kc,
                                          int tid, bool a_cg,
                                          float4& av, float4& w0v, float4& w1v) {
    int b = tid >> 2, q = tid & 3;
    const float4* ap = (const float4*)(Ag + (size_t)b * lda + kc + q * 4);
    av = a_cg ? __ldcg(ap) : *ap;
    int kk = tid >> 4, c = tid & 15;
    const float* wp = Wrow + (size_t)(kc + kk) * NG;
    w0v = *(const float4*)(wp + 4 * c);
    w1v = *(const float4*)(wp + 4 * c + 64);
}

__device__ __forceinline__ void store_frag(float (&A_s)[16][68], float (&W_s)[16][128],
                                           int tid, const float4& av,
                                           const float4& w0v, const float4& w1v) {
    int b = tid >> 2, q = tid & 3;
    A_s[q * 4 + 0][b] = av.x; A_s[q * 4 + 1][b] = av.y;
    A_s[q * 4 + 2][b] = av.z; A_s[q * 4 + 3][b] = av.w;
    int kk = tid >> 4, c = tid & 15;
    *(float4*)&W_s[kk][4 * c]      = w0v;
    *(float4*)&W_s[kk][4 * c + 64] = w1v;
}

template <int KT>
__device__ __forceinline__ void gemm_acc(float (&acc)[8][4],
                                         const float* __restrict__ Ag, int lda,
                                         const float* __restrict__ Wrow,
                                         float (&A_s)[16][68], float (&W_s)[16][128],
                                         int tid, int tx, int ty, bool a_cg) {
    float4 av, w0v, w1v;
    load_frag(Ag, lda, Wrow, 0, tid, a_cg, av, w0v, w1v);
#pragma unroll 1
    for (int kt = 0; kt < KT; ++kt) {
        __syncthreads();
        store_frag(A_s, W_s, tid, av, w0v, w1v);
        __syncthreads();
        if (kt + 1 < KT) load_frag(Ag, lda, Wrow, (kt + 1) * 16, tid, a_cg, av, w0v, w1v);
#pragma unroll
        for (int kk = 0; kk < 16; ++kk) {
            float4 a0 = *(const float4*)&A_s[kk][ty * 8];
            float4 a1 = *(const float4*)&A_s[kk][ty * 8 + 4];
            float w0 = W_s[kk][tx],      w1 = W_s[kk][32 + tx];
            float w2 = W_s[kk][64 + tx], w3 = W_s[kk][96 + tx];
            float aa[8] = {a0.x, a0.y, a0.z, a0.w, a1.x, a1.y, a1.z, a1.w};
#pragma unroll
            for (int e = 0; e < 8; ++e) {
                acc[e][0] = fmaf(aa[e], w0, acc[e][0]);
                acc[e][1] = fmaf(aa[e], w1, acc[e][1]);
                acc[e][2] = fmaf(aa[e], w2, acc[e][2]);
                acc[e][3] = fmaf(aa[e], w3, acc[e][3]);
            }
        }
    }
}

__device__ __forceinline__ float sigm(float x) { return 1.f / (1.f + expf(-x)); }

// -------------------- kernel 3: persistent fused 2-layer LSTM --------------
__global__ void __launch_bounds__(256, 1) lstm_kernel(
    const float* __restrict__ h0in, const float* __restrict__ c0in,
    const float* __restrict__ fcw, const float* __restrict__ fcb,
    const float* __restrict__ decw, const float* __restrict__ decb,
    float* __restrict__ out) {
    __shared__ __align__(16) float A_s[16][68];
    __shared__ __align__(16) float W_s[16][128];

    const int tid = threadIdx.x;
    const int tx = tid & 31, ty = tid >> 5;
    const int bi = blockIdx.x >> 3;   // batch group 0..15
    const int hi = blockIdx.x & 7;    // hidden slice 0..7
    const int jg = hi * 32 + tx;      // global hidden index owned by this thread
    const int b0 = bi * 64 + ty * 8;  // first batch row of this thread

    float bias0[4], bias1[4];
#pragma unroll
    for (int g = 0; g < 4; ++g) {
        bias0[g] = g_bias[hi * 128 + g * 32 + tx];
        bias1[g] = g_bias[NG + hi * 128 + g * 32 + tx];
    }

    float c0r[8], c1r[8];
#pragma unroll
    for (int e = 0; e < 8; ++e) {
        int b = b0 + e;
        c0r[e] = c0in[b * NH + jg];
        c1r[e] = c0in[Bsz * NH + b * NH + jg];
        g_H0[b * NH + jg] = h0in[b * NH + jg];
        g_H1[b * NH + jg] = h0in[Bsz * NH + b * NH + jg];
    }
    group_barrier(bi);

    const float* W0x = g_WT + hi * 128;                            // rows [0,32)
    const float* W0h = g_WT + (size_t)KX * NG + hi * 128;          // rows [32,288)
    const float* W1x = g_WT + (size_t)(KX + NH) * NG + hi * 128;   // rows [288,544)
    const float* W1h = g_WT + (size_t)(KX + 2 * NH) * NG + hi * 128;

    int p = 0;
    for (int t = 0; t < Tst; ++t) {
        // ---------------- layer 0 ----------------
        float acc[8][4];
#pragma unroll
        for (int e = 0; e < 8; ++e)
#pragma unroll
            for (int g = 0; g < 4; ++g) acc[e][g] = bias0[g];

        gemm_acc<2>(acc, g_X + ((size_t)t * Bsz + bi * 64) * KX, KX, W0x,
                    A_s, W_s, tid, tx, ty, false);
        gemm_acc<16>(acc, g_H0 + (size_t)p * Bsz * NH + bi * 64 * NH, NH, W0h,
                     A_s, W_s, tid, tx, ty, true);
#pragma unroll
        for (int e = 0; e < 8; ++e) {
            float ig = sigm(acc[e][0]);
            float fg = sigm(acc[e][1]);
            float gg = tanhf(acc[e][2]);
            float og = sigm(acc[e][3]);
            float c = fmaf(fg, c0r[e], ig * gg);
            c0r[e] = c;
            g_H0[(size_t)(1 - p) * Bsz * NH + (b0 + e) * NH + jg] = og * tanhf(c);
        }
        group_barrier(bi);

        // ---------------- layer 1 ----------------
#pragma unroll
        for (int e = 0; e < 8; ++e)
#pragma unroll
            for (int g = 0; g < 4; ++g) acc[e][g] = bias1[g];

        gemm_acc<16>(acc, g_H0 + (size_t)(1 - p) * Bsz * NH + bi * 64 * NH, NH, W1x,
                     A_s, W_s, tid, tx, ty, true);
        gemm_acc<16>(acc, g_H1 + (size_t)p * Bsz * NH + bi * 64 * NH, NH, W1h,
                     A_s, W_s, tid, tx, ty, true);
#pragma unroll
        for (int e = 0; e < 8; ++e) {
            float ig = sigm(acc[e][0]);
            float fg = sigm(acc[e][1]);
            float gg = tanhf(acc[e][2]);
            float og = sigm(acc[e][3]);
            float c = fmaf(fg, c1r[e], ig * gg);
            c1r[e] = c;
            g_H1[(size_t)(1 - p) * Bsz * NH + (b0 + e) * NH + jg] = og * tanhf(c);
        }
        group_barrier(bi);
        p ^= 1;
    }

    // ---------------- outputs ----------------
    float* outh = out + 2 * Bsz;
    float* outc = outh + 2 * Bsz * NH;
#pragma unroll
    for (int e = 0; e < 8; ++e) {
        int b = b0 + e;
        outh[b * NH + jg]            = g_H0[(size_t)p * Bsz * NH + b * NH + jg];
        outh[Bsz * NH + b * NH + jg] = g_H1[(size_t)p * Bsz * NH + b * NH + jg];
        outc[b * NH + jg]            = c0r[e];
        outc[Bsz * NH + b * NH + jg] = c1r[e];
    }

    // decoded head: only last timestep's layer1 h matters
    if (hi == 0 && tid < 64) {
        int b = bi * 64 + tid;
        const float* h1 = g_H1 + (size_t)p * Bsz * NH + b * NH;
        float d0 = decb[0], d1 = decb[1];
#pragma unroll 1
        for (int m = 0; m < 10; ++m) {
            float s = fcb[m];
            for (int j = 0; j < 256; ++j) s = fmaf(__ldcg(h1 + j), fcw[m * 256 + j], s);
            s = fmaxf(s, 0.f);
            d0 = fmaf(s, decw[m], d0);
            d1 = fmaf(s, decw[10 + m], d1);
        }
        out[b] = d0;           // decoded.T[0][b]
        out[Bsz + b] = d1;     // decoded.T[1][b]
    }
}

// -------------------- launch --------------------
extern "C" void kernel_launch(void* const* d_in, const int* in_sizes, int n_in,
                              void* d_out, int out_size) {
    const int*   input = (const int*)  d_in[0];
    const float* h0    = (const float*)d_in[1];
    const float* c0    = (const float*)d_in[2];
    const float* emb   = (const float*)d_in[3];
    const float* fcw   = (const float*)d_in[4];
    const float* fcb   = (const float*)d_in[5];
    const float* decw  = (const float*)d_in[6];
    const float* decb  = (const float*)d_in[7];
    const float* Wih0  = (const float*)d_in[8];
    const float* Whh0  = (const float*)d_in[9];
    const float* bih0  = (const float*)d_in[10];
    const float* bhh0  = (const float*)d_in[11];
    const float* Wih1  = (const float*)d_in[12];
    const float* Whh1  = (const float*)d_in[13];
    const float* bih1  = (const float*)d_in[14];
    const float* bhh1  = (const float*)d_in[15];
    float* out = (float*)d_out;

    long nX = (long)Tst * Bsz * KX;
    gather_emb_kernel<<<(unsigned)((nX + 255) / 256), 256>>>(input, emb);

    int nW = (KX + 3 * NH) * NG + 2 * NG;
    prep_weights_kernel<<<(nW + 255) / 256, 256>>>(Wih0, Whh0, bih0, bhh0,
                                                   Wih1, Whh1, bih1, bhh1);

    lstm_kernel<<<NCTA, 256>>>(h0, c0, fcw, fcb, decw, decb, out);
}

// round 3
// speedup vs baseline: 1.0040x; 1.0040x over previous
#include <cuda_runtime.h>

// ---------------------------------------------------------------------------
// RNNSent: 2-layer LSTM (T=300 steps after the .view trick), B=1024, NHID=256
// Layer0 in-dim 25 (padded to 32), Layer1 in-dim 256.
// Outputs: decoded.T [2,1024] ++ h [2,1024,256] ++ c [2,1024,256]  (fp32)
// ---------------------------------------------------------------------------

#define Bsz   1024
#define Tst   300
#define NH    256
#define NG    1024        // 4*NH gate rows
#define KX    32          // padded layer0 input dim (25 -> 32)
#define GSIZE 8           // CTAs per batch-group (hidden split 256/32)
#define NGRP  16          // batch groups (1024/64)
#define NCTA  128

// -------------------- device scratch (static, no allocations) --------------
__device__ float g_X[(size_t)Tst * Bsz * KX];              // [t][b][kx] padded emb
// rows: [0,32)=Wih0T, [32,288)=Whh0T, [288,544)=Wih1T, [544,800)=Whh1T
// each row has 1024 cols permuted so CTA hi's 128 gate-cols are contiguous:
// col' = hi*128 + g*32 + j  for gate row r = g*256 + hi*32 + j
__device__ float g_WT[(size_t)(KX + 3 * NH) * NG];
__device__ float g_bias[2 * NG];                            // permuted b_ih+b_hh
__device__ float g_H0[2 * Bsz * NH];                        // double-buffered h, layer0
__device__ float g_H1[2 * Bsz * NH];                        // layer1
__device__ unsigned g_bar_count[NGRP];
__device__ unsigned g_bar_gen[NGRP];

// -------------------- kernel 1: embedding gather + pad ---------------------
__global__ void gather_emb_kernel(const int* __restrict__ input,
                                  const float* __restrict__ emb) {
    long idx = (long)blockIdx.x * blockDim.x + threadIdx.x;
    long total = (long)Tst * Bsz * KX;
    if (idx >= total) return;
    int k = (int)(idx & (KX - 1));
    long tb = idx >> 5;
    int b = (int)(tb & (Bsz - 1));
    int t = (int)(tb >> 10);
    float v = 0.f;
    if (k < 25) {
        // x[t][b][k] = flat E index t*25600 + b*25 + k over emb[25][1024][300]
        long flat = (long)t * (Bsz * 25) + b * 25 + k;
        int s  = (int)(flat / (Bsz * 300));
        int rr = (int)(flat % (Bsz * 300));
        int bb = rr / 300;
        int e  = rr % 300;
        int tok = input[bb * 25 + s];
        v = emb[(long)tok * 300 + e];
    }
    g_X[idx] = v;
}

// -------------------- kernel 2: weight transpose + permute -----------------
__global__ void prep_weights_kernel(
    const float* __restrict__ Wih0, const float* __restrict__ Whh0,
    const float* __restrict__ bih0, const float* __restrict__ bhh0,
    const float* __restrict__ Wih1, const float* __restrict__ Whh1,
    const float* __restrict__ bih1, const float* __restrict__ bhh1) {
    int idx = blockIdx.x * blockDim.x + threadIdx.x;
    const int total = (KX + 3 * NH) * NG;   // 819200
    if (idx < total) {
        int row  = idx >> 10;
        int colp = idx & 1023;
        int hi = colp >> 7, g = (colp >> 5) & 3, j = colp & 31;
        int r = g * 256 + hi * 32 + j;      // original gate row
        float v;
        if (row < KX)               { int k = row;               v = (k < 25) ? Wih0[r * 25 + k] : 0.f; }
        else if (row < KX + NH)     { int k = row - KX;          v = Whh0[r * 256 + k]; }
        else if (row < KX + 2 * NH) { int k = row - (KX + NH);   v = Wih1[r * 256 + k]; }
        else                        { int k = row - (KX + 2*NH); v = Whh1[r * 256 + k]; }
        g_WT[idx] = v;
    } else if (idx < total + 2 * NG) {
        int i2 = idx - total;
        int l = i2 >> 10, colp = i2 & 1023;
        int hi = colp >> 7, g = (colp >> 5) & 3, j = colp & 31;
        int r = g * 256 + hi * 32 + j;
        g_bias[i2] = (l == 0) ? (bih0[r] + bhh0[r]) : (bih1[r] + bhh1[r]);
    }
}

// -------------------- group barrier (8 co-resident CTAs) -------------------
__device__ __forceinline__ void group_barrier(int grp) {
    __syncthreads();
    if (threadIdx.x == 0) {
        __threadfence();   // release: make this CTA's h writes visible (gpu scope)
        volatile unsigned* genp = &g_bar_gen[grp];
        unsigned gen = *genp;
        unsigned old = atomicAdd(&g_bar_count[grp], 1u);
        if (old == GSIZE - 1) {
            ((volatile unsigned*)&g_bar_count[grp])[0] = 0u;
            __threadfence();
            atomicExch(&g_bar_gen[grp], gen + 1u);
        } else {
            while (*genp == gen) { __nanosleep(64); }
        }
        __threadfence();   // acquire: L1 invalidate before reading peers' h
    }
    __syncthreads();
}

// -------------------- fp32 register-tiled GEMM fragment --------------------
// CTA computes G[64 batch, 128 gatecols] accumulating over K.
// Thread (ty in [0,8), tx in [0,32)): 8 batch rows (b0=ty*8) x 4 gates of j=tx.
__device__ __forceinline__ void load_frag(const float* __restrict__ Ag, int lda,
                                          const float* __restrict__ Wrow, int kc,
                                          int tid, bool a_cg,
                                          float4& av, float4& w0v, float4& w1v) {
    int b = tid >> 2, q = tid & 3;
    const float4* ap = (const float4*)(Ag + (size_t)b * lda + kc + q * 4);
    av = a_cg ? __ldcg(ap) : *ap;
    int kk = tid >> 4, c = tid & 15;
    const float* wp = Wrow + (size_t)(kc + kk) * NG;
    w0v = *(const float4*)(wp + 4 * c);
    w1v = *(const float4*)(wp + 4 * c + 64);
}

__device__ __forceinline__ void store_frag(float (&A_s)[16][68], float (&W_s)[16][128],
                                           int tid, const float4& av,
                                           const float4& w0v, const float4& w1v) {
    int b = tid >> 2, q = tid & 3;
    A_s[q * 4 + 0][b] = av.x; A_s[q * 4 + 1][b] = av.y;
    A_s[q * 4 + 2][b] = av.z; A_s[q * 4 + 3][b] = av.w;
    int kk = tid >> 4, c = tid & 15;
    *(float4*)&W_s[kk][4 * c]      = w0v;
    *(float4*)&W_s[kk][4 * c + 64] = w1v;
}

template <int KT>
__device__ __forceinline__ void gemm_acc(float (&acc)[8][4],
                                         const float* __restrict__ Ag, int lda,
                                         const float* __restrict__ Wrow,
                                         float (&A_s)[16][68], float (&W_s)[16][128],
                                         int tid, int tx, int ty, bool a_cg) {
    float4 av, w0v, w1v;
    load_frag(Ag, lda, Wrow, 0, tid, a_cg, av, w0v, w1v);
#pragma unroll 1
    for (int kt = 0; kt < KT; ++kt) {
        __syncthreads();
        store_frag(A_s, W_s, tid, av, w0v, w1v);
        __syncthreads();
        if (kt + 1 < KT) load_frag(Ag, lda, Wrow, (kt + 1) * 16, tid, a_cg, av, w0v, w1v);
#pragma unroll
        for (int kk = 0; kk < 16; ++kk) {
            float4 a0 = *(const float4*)&A_s[kk][ty * 8];
            float4 a1 = *(const float4*)&A_s[kk][ty * 8 + 4];
            float w0 = W_s[kk][tx],      w1 = W_s[kk][32 + tx];
            float w2 = W_s[kk][64 + tx], w3 = W_s[kk][96 + tx];
            float aa[8] = {a0.x, a0.y, a0.z, a0.w, a1.x, a1.y, a1.z, a1.w};
#pragma unroll
            for (int e = 0; e < 8; ++e) {
                acc[e][0] = fmaf(aa[e], w0, acc[e][0]);
                acc[e][1] = fmaf(aa[e], w1, acc[e][1]);
                acc[e][2] = fmaf(aa[e], w2, acc[e][2]);
                acc[e][3] = fmaf(aa[e], w3, acc[e][3]);
            }
        }
    }
}

__device__ __forceinline__ float sigm(float x) { return 1.f / (1.f + expf(-x)); }

// -------------------- kernel 3: persistent fused 2-layer LSTM --------------
__global__ void __launch_bounds__(256, 1) lstm_kernel(
    const float* __restrict__ h0in, const float* __restrict__ c0in,
    const float* __restrict__ fcw, const float* __restrict__ fcb,
    const float* __restrict__ decw, const float* __restrict__ decb,
    float* __restrict__ out) {
    __shared__ __align__(16) float A_s[16][68];
    __shared__ __align__(16) float W_s[16][128];

    const int tid = threadIdx.x;
    const int tx = tid & 31, ty = tid >> 5;
    const int bi = blockIdx.x >> 3;   // batch group 0..15
    const int hi = blockIdx.x & 7;    // hidden slice 0..7
    const int jg = hi * 32 + tx;      // global hidden index owned by this thread
    const int b0 = bi * 64 + ty * 8;  // first batch row of this thread

    float bias0[4], bias1[4];
#pragma unroll
    for (int g = 0; g < 4; ++g) {
        bias0[g] = g_bias[hi * 128 + g * 32 + tx];
        bias1[g] = g_bias[NG + hi * 128 + g * 32 + tx];
    }

    float c0r[8], c1r[8];
#pragma unroll
    for (int e = 0; e < 8; ++e) {
        int b = b0 + e;
        c0r[e] = c0in[b * NH + jg];
        c1r[e] = c0in[Bsz * NH + b * NH + jg];
        g_H0[b * NH + jg] = h0in[b * NH + jg];
        g_H1[b * NH + jg] = h0in[Bsz * NH + b * NH + jg];
    }
    group_barrier(bi);

    const float* W0x = g_WT + hi * 128;                            // rows [0,32)
    const float* W0h = g_WT + (size_t)KX * NG + hi * 128;          // rows [32,288)
    const float* W1x = g_WT + (size_t)(KX + NH) * NG + hi * 128;   // rows [288,544)
    const float* W1h = g_WT + (size_t)(KX + 2 * NH) * NG + hi * 128;

    int p = 0;
    for (int t = 0; t < Tst; ++t) {
        // ---------------- layer 0 ----------------
        float acc[8][4];
#pragma unroll
        for (int e = 0; e < 8; ++e)
#pragma unroll
            for (int g = 0; g < 4; ++g) acc[e][g] = bias0[g];

        gemm_acc<2>(acc, g_X + ((size_t)t * Bsz + bi * 64) * KX, KX, W0x,
                    A_s, W_s, tid, tx, ty, false);
        gemm_acc<16>(acc, g_H0 + (size_t)p * Bsz * NH + bi * 64 * NH, NH, W0h,
                     A_s, W_s, tid, tx, ty, true);
#pragma unroll
        for (int e = 0; e < 8; ++e) {
            float ig = sigm(acc[e][0]);
            float fg = sigm(acc[e][1]);
            float gg = tanhf(acc[e][2]);
            float og = sigm(acc[e][3]);
            float c = fmaf(fg, c0r[e], ig * gg);
            c0r[e] = c;
            g_H0[(size_t)(1 - p) * Bsz * NH + (b0 + e) * NH + jg] = og * tanhf(c);
        }
        group_barrier(bi);

        // ---------------- layer 1 ----------------
#pragma unroll
        for (int e = 0; e < 8; ++e)
#pragma unroll
            for (int g = 0; g < 4; ++g) acc[e][g] = bias1[g];

        gemm_acc<16>(acc, g_H0 + (size_t)(1 - p) * Bsz * NH + bi * 64 * NH, NH, W1x,
                     A_s, W_s, tid, tx, ty, true);
        gemm_acc<16>(acc, g_H1 + (size_t)p * Bsz * NH + bi * 64 * NH, NH, W1h,
                     A_s, W_s, tid, tx, ty, true);
#pragma unroll
        for (int e = 0; e < 8; ++e) {
            float ig = sigm(acc[e][0]);
            float fg = sigm(acc[e][1]);
            float gg = tanhf(acc[e][2]);
            float og = sigm(acc[e][3]);
            float c = fmaf(fg, c1r[e], ig * gg);
            c1r[e] = c;
            g_H1[(size_t)(1 - p) * Bsz * NH + (b0 + e) * NH + jg] = og * tanhf(c);
        }
        group_barrier(bi);
        p ^= 1;
    }

    // ---------------- outputs ----------------
    float* outh = out + 2 * Bsz;
    float* outc = outh + 2 * Bsz * NH;
#pragma unroll
    for (int e = 0; e < 8; ++e) {
        int b = b0 + e;
        outh[b * NH + jg]            = g_H0[(size_t)p * Bsz * NH + b * NH + jg];
        outh[Bsz * NH + b * NH + jg] = g_H1[(size_t)p * Bsz * NH + b * NH + jg];
        outc[b * NH + jg]            = c0r[e];
        outc[Bsz * NH + b * NH + jg] = c1r[e];
    }

    // decoded head: only last timestep's layer1 h matters
    if (hi == 0 && tid < 64) {
        int b = bi * 64 + tid;
        const float* h1 = g_H1 + (size_t)p * Bsz * NH + b * NH;
        float d0 = decb[0], d1 = decb[1];
#pragma unroll 1
        for (int m = 0; m < 10; ++m) {
            float s = fcb[m];
            for (int j = 0; j < 256; ++j) s = fmaf(__ldcg(h1 + j), fcw[m * 256 + j], s);
            s = fmaxf(s, 0.f);
            d0 = fmaf(s, decw[m], d0);
            d1 = fmaf(s, decw[10 + m], d1);
        }
        out[b] = d0;           // decoded.T[0][b]
        out[Bsz + b] = d1;     // decoded.T[1][b]
    }
}

// -------------------- launch --------------------
extern "C" void kernel_launch(void* const* d_in, const int* in_sizes, int n_in,
                              void* d_out, int out_size) {
    const int*   input = (const int*)  d_in[0];
    const float* h0    = (const float*)d_in[1];
    const float* c0    = (const float*)d_in[2];
    const float* emb   = (const float*)d_in[3];
    const float* fcw   = (const float*)d_in[4];
    const float* fcb   = (const float*)d_in[5];
    const float* decw  = (const float*)d_in[6];
    const float* decb  = (const float*)d_in[7];
    const float* Wih0  = (const float*)d_in[8];
    const float* Whh0  = (const float*)d_in[9];
    const float* bih0  = (const float*)d_in[10];
    const float* bhh0  = (const float*)d_in[11];
    const float* Wih1  = (const float*)d_in[12];
    const float* Whh1  = (const float*)d_in[13];
    const float* bih1  = (const float*)d_in[14];
    const float* bhh1  = (const float*)d_in[15];
    float* out = (float*)d_out;

    long nX = (long)Tst * Bsz * KX;
    gather_emb_kernel<<<(unsigned)((nX + 255) / 256), 256>>>(input, emb);

    int nW = (KX + 3 * NH) * NG + 2 * NG;
    prep_weights_kernel<<<(nW + 255) / 256, 256>>>(Wih0, Whh0, bih0, bhh0,
                                                   Wih1, Whh1, bih1, bhh1);

    lstm_kernel<<<NCTA, 256>>>(h0, c0, fcw, fcb, decw, decb, out);
}

// round 4
// speedup vs baseline: 1.1273x; 1.1229x over previous
#include <cuda_runtime.h>

// ---------------------------------------------------------------------------
// RNNSent: 2-layer LSTM (T=300 steps after the .view trick), B=1024, NHID=256
// Round 3: packed fp32x2 FFMA2 mainloop (exact fp32, 2 FMA/issue) + K-tile 32.
// Outputs: decoded.T [2,1024] ++ h [2,1024,256] ++ c [2,1024,256]  (fp32)
// ---------------------------------------------------------------------------

#define Bsz   1024
#define Tst   300
#define NH    256
#define NG    1024        // 4*NH gate rows
#define KX    32          // padded layer0 input dim (25 -> 32)
#define GSIZE 8           // CTAs per batch-group (hidden split 256/32)
#define NGRP  16          // batch groups (1024/64)
#define NCTA  128

// -------------------- device scratch (static, no allocations) --------------
__device__ float g_X[(size_t)Tst * Bsz * KX];              // [t][b][kx] padded emb
// rows: [0,32)=Wih0T, [32,288)=Whh0T, [288,544)=Wih1T, [544,800)=Whh1T
// col' = hi*128 + g*32 + j  for gate row r = g*256 + hi*32 + j
__device__ float g_WT[(size_t)(KX + 3 * NH) * NG];
__device__ float g_bias[2 * NG];                            // permuted b_ih+b_hh
__device__ float g_H0[2 * Bsz * NH];                        // double-buffered h, layer0
__device__ float g_H1[2 * Bsz * NH];                        // layer1
__device__ unsigned g_bar_count[NGRP];
__device__ unsigned g_bar_gen[NGRP];

// -------------------- packed f32x2 helpers ----------------------------------
__device__ __forceinline__ unsigned long long dup2(float w) {
    unsigned long long r;
    asm("mov.b64 %0, {%1, %1};" : "=l"(r) : "f"(w));
    return r;
}
__device__ __forceinline__ void ffma2(unsigned long long& d, unsigned long long a,
                                      unsigned long long b) {
    asm("fma.rn.f32x2 %0, %1, %2, %0;" : "+l"(d) : "l"(a), "l"(b));
}
__device__ __forceinline__ float2 unpack2(unsigned long long v) {
    float2 f;
    asm("mov.b64 {%0, %1}, %2;" : "=f"(f.x), "=f"(f.y) : "l"(v));
    return f;
}

// -------------------- kernel 1: embedding gather + pad ---------------------
__global__ void gather_emb_kernel(const int* __restrict__ input,
                                  const float* __restrict__ emb) {
    long idx = (long)blockIdx.x * blockDim.x + threadIdx.x;
    long total = (long)Tst * Bsz * KX;
    if (idx >= total) return;
    int k = (int)(idx & (KX - 1));
    long tb = idx >> 5;
    int b = (int)(tb & (Bsz - 1));
    int t = (int)(tb >> 10);
    float v = 0.f;
    if (k < 25) {
        long flat = (long)t * (Bsz * 25) + b * 25 + k;
        int s  = (int)(flat / (Bsz * 300));
        int rr = (int)(flat % (Bsz * 300));
        int bb = rr / 300;
        int e  = rr % 300;
        int tok = input[bb * 25 + s];
        v = emb[(long)tok * 300 + e];
    }
    g_X[idx] = v;
}

// -------------------- kernel 2: weight transpose + permute -----------------
__global__ void prep_weights_kernel(
    const float* __restrict__ Wih0, const float* __restrict__ Whh0,
    const float* __restrict__ bih0, const float* __restrict__ bhh0,
    const float* __restrict__ Wih1, const float* __restrict__ Whh1,
    const float* __restrict__ bih1, const float* __restrict__ bhh1) {
    int idx = blockIdx.x * blockDim.x + threadIdx.x;
    const int total = (KX + 3 * NH) * NG;   // 819200
    if (idx < total) {
        int row  = idx >> 10;
        int colp = idx & 1023;
        int hi = colp >> 7, g = (colp >> 5) & 3, j = colp & 31;
        int r = g * 256 + hi * 32 + j;      // original gate row
        float v;
        if (row < KX)               { int k = row;               v = (k < 25) ? Wih0[r * 25 + k] : 0.f; }
        else if (row < KX + NH)     { int k = row - KX;          v = Whh0[r * 256 + k]; }
        else if (row < KX + 2 * NH) { int k = row - (KX + NH);   v = Wih1[r * 256 + k]; }
        else                        { int k = row - (KX + 2*NH); v = Whh1[r * 256 + k]; }
        g_WT[idx] = v;
    } else if (idx < total + 2 * NG) {
        int i2 = idx - total;
        int l = i2 >> 10, colp = i2 & 1023;
        int hi = colp >> 7, g = (colp >> 5) & 3, j = colp & 31;
        int r = g * 256 + hi * 32 + j;
        g_bias[i2] = (l == 0) ? (bih0[r] + bhh0[r]) : (bih1[r] + bhh1[r]);
    }
}

// -------------------- group barrier (8 co-resident CTAs) -------------------
__device__ __forceinline__ void group_barrier(int grp) {
    __syncthreads();
    if (threadIdx.x == 0) {
        __threadfence();   // release: make this CTA's h writes visible
        volatile unsigned* genp = &g_bar_gen[grp];
        unsigned gen = *genp;
        unsigned old = atomicAdd(&g_bar_count[grp], 1u);
        if (old == GSIZE - 1) {
            ((volatile unsigned*)&g_bar_count[grp])[0] = 0u;
            __threadfence();
            atomicExch(&g_bar_gen[grp], gen + 1u);
        } else {
            while (*genp == gen) { __nanosleep(64); }
        }
        __threadfence();   // acquire
    }
    __syncthreads();
}

// -------------------- fp32x2 register-tiled GEMM fragment ------------------
// CTA computes G[64 batch, 128 gatecols], K-tile = 32.
// Thread (ty in [0,8), tx in [0,32)): 8 batch rows (as 4 f32x2 pairs) x 4 gates.
struct Frag {
    float4 a0, a1;                 // A: (b, kq*4..) and (b, 16+kq*4..)
    float4 w00, w01, w10, w11;     // W rows kk, kk+16; col halves 0 / +64
};

__device__ __forceinline__ void load_frag(const float* __restrict__ Ag, int lda,
                                          const float* __restrict__ Wrow, int kc,
                                          int tid, bool a_cg, Frag& f) {
    int b = tid >> 2, q = tid & 3;
    const float4* ap0 = (const float4*)(Ag + (size_t)b * lda + kc + q * 4);
    const float4* ap1 = (const float4*)(Ag + (size_t)b * lda + kc + 16 + q * 4);
    f.a0 = a_cg ? __ldcg(ap0) : *ap0;
    f.a1 = a_cg ? __ldcg(ap1) : *ap1;
    int kk = tid >> 4, c = tid & 15;
    const float* wp0 = Wrow + (size_t)(kc + kk) * NG;
    const float* wp1 = Wrow + (size_t)(kc + kk + 16) * NG;
    f.w00 = *(const float4*)(wp0 + 4 * c);
    f.w01 = *(const float4*)(wp0 + 4 * c + 64);
    f.w10 = *(const float4*)(wp1 + 4 * c);
    f.w11 = *(const float4*)(wp1 + 4 * c + 64);
}

__device__ __forceinline__ void store_frag(float (&A_s)[32][68], float (&W_s)[32][128],
                                           int tid, const Frag& f) {
    int b = tid >> 2, q = tid & 3;
    A_s[q * 4 + 0][b] = f.a0.x; A_s[q * 4 + 1][b] = f.a0.y;
    A_s[q * 4 + 2][b] = f.a0.z; A_s[q * 4 + 3][b] = f.a0.w;
    A_s[16 + q * 4 + 0][b] = f.a1.x; A_s[16 + q * 4 + 1][b] = f.a1.y;
    A_s[16 + q * 4 + 2][b] = f.a1.z; A_s[16 + q * 4 + 3][b] = f.a1.w;
    int kk = tid >> 4, c = tid & 15;
    *(float4*)&W_s[kk][4 * c]           = f.w00;
    *(float4*)&W_s[kk][4 * c + 64]      = f.w01;
    *(float4*)&W_s[kk + 16][4 * c]      = f.w10;
    *(float4*)&W_s[kk + 16][4 * c + 64] = f.w11;
}

template <int KT>   // KT in units of 32-k tiles
__device__ __forceinline__ void gemm_acc(unsigned long long (&acc2)[4][4],
                                         const float* __restrict__ Ag, int lda,
                                         const float* __restrict__ Wrow,
                                         float (&A_s)[32][68], float (&W_s)[32][128],
                                         int tid, int tx, int ty, bool a_cg) {
    Frag f;
    load_frag(Ag, lda, Wrow, 0, tid, a_cg, f);
#pragma unroll 1
    for (int kt = 0; kt < KT; ++kt) {
        __syncthreads();
        store_frag(A_s, W_s, tid, f);
        __syncthreads();
        if (kt + 1 < KT) load_frag(Ag, lda, Wrow, (kt + 1) * 32, tid, a_cg, f);
#pragma unroll
        for (int kk = 0; kk < 32; ++kk) {
            const ulonglong2* ap = (const ulonglong2*)&A_s[kk][ty * 8];
            ulonglong2 aA = ap[0];   // pairs (e0,e1), (e2,e3)
            ulonglong2 aB = ap[1];   // pairs (e4,e5), (e6,e7)
            unsigned long long w0 = dup2(W_s[kk][tx]);
            unsigned long long w1 = dup2(W_s[kk][32 + tx]);
            unsigned long long w2 = dup2(W_s[kk][64 + tx]);
            unsigned long long w3 = dup2(W_s[kk][96 + tx]);
            ffma2(acc2[0][0], aA.x, w0); ffma2(acc2[0][1], aA.x, w1);
            ffma2(acc2[0][2], aA.x, w2); ffma2(acc2[0][3], aA.x, w3);
            ffma2(acc2[1][0], aA.y, w0); ffma2(acc2[1][1], aA.y, w1);
            ffma2(acc2[1][2], aA.y, w2); ffma2(acc2[1][3], aA.y, w3);
            ffma2(acc2[2][0], aB.x, w0); ffma2(acc2[2][1], aB.x, w1);
            ffma2(acc2[2][2], aB.x, w2); ffma2(acc2[2][3], aB.x, w3);
            ffma2(acc2[3][0], aB.y, w0); ffma2(acc2[3][1], aB.y, w1);
            ffma2(acc2[3][2], aB.y, w2); ffma2(acc2[3][3], aB.y, w3);
        }
    }
}

__device__ __forceinline__ float sigm(float x) { return 1.f / (1.f + expf(-x)); }

// -------------------- kernel 3: persistent fused 2-layer LSTM --------------
__global__ void __launch_bounds__(256, 1) lstm_kernel(
    const float* __restrict__ h0in, const float* __restrict__ c0in,
    const float* __restrict__ fcw, const float* __restrict__ fcb,
    const float* __restrict__ decw, const float* __restrict__ decb,
    float* __restrict__ out) {
    __shared__ __align__(16) float A_s[32][68];
    __shared__ __align__(16) float W_s[32][128];

    const int tid = threadIdx.x;
    const int tx = tid & 31, ty = tid >> 5;
    const int bi = blockIdx.x >> 3;   // batch group 0..15
    const int hi = blockIdx.x & 7;    // hidden slice 0..7
    const int jg = hi * 32 + tx;      // global hidden index owned by this thread
    const int b0 = bi * 64 + ty * 8;  // first batch row of this thread

    unsigned long long bias0d[4], bias1d[4];
#pragma unroll
    for (int g = 0; g < 4; ++g) {
        bias0d[g] = dup2(g_bias[hi * 128 + g * 32 + tx]);
        bias1d[g] = dup2(g_bias[NG + hi * 128 + g * 32 + tx]);
    }

    float c0r[8], c1r[8];
#pragma unroll
    for (int e = 0; e < 8; ++e) {
        int b = b0 + e;
        c0r[e] = c0in[b * NH + jg];
        c1r[e] = c0in[Bsz * NH + b * NH + jg];
        g_H0[b * NH + jg] = h0in[b * NH + jg];
        g_H1[b * NH + jg] = h0in[Bsz * NH + b * NH + jg];
    }
    group_barrier(bi);

    const float* W0x = g_WT + hi * 128;
    const float* W0h = g_WT + (size_t)KX * NG + hi * 128;
    const float* W1x = g_WT + (size_t)(KX + NH) * NG + hi * 128;
    const float* W1h = g_WT + (size_t)(KX + 2 * NH) * NG + hi * 128;

    int p = 0;
    for (int t = 0; t < Tst; ++t) {
        // ---------------- layer 0 ----------------
        unsigned long long acc2[4][4];
#pragma unroll
        for (int pr = 0; pr < 4; ++pr)
#pragma unroll
            for (int g = 0; g < 4; ++g) acc2[pr][g] = bias0d[g];

        gemm_acc<1>(acc2, g_X + ((size_t)t * Bsz + bi * 64) * KX, KX, W0x,
                    A_s, W_s, tid, tx, ty, false);
        gemm_acc<8>(acc2, g_H0 + (size_t)p * Bsz * NH + bi * 64 * NH, NH, W0h,
                    A_s, W_s, tid, tx, ty, true);
#pragma unroll
        for (int pr = 0; pr < 4; ++pr) {
            float2 vi = unpack2(acc2[pr][0]);
            float2 vf = unpack2(acc2[pr][1]);
            float2 vg = unpack2(acc2[pr][2]);
            float2 vo = unpack2(acc2[pr][3]);
            float gi[2] = {vi.x, vi.y}, gf[2] = {vf.x, vf.y};
            float gg[2] = {vg.x, vg.y}, go[2] = {vo.x, vo.y};
#pragma unroll
            for (int h = 0; h < 2; ++h) {
                int e = 2 * pr + h;
                float c = fmaf(sigm(gf[h]), c0r[e], sigm(gi[h]) * tanhf(gg[h]));
                c0r[e] = c;
                g_H0[(size_t)(1 - p) * Bsz * NH + (b0 + e) * NH + jg] =
                    sigm(go[h]) * tanhf(c);
            }
        }
        group_barrier(bi);

        // ---------------- layer 1 ----------------
#pragma unroll
        for (int pr = 0; pr < 4; ++pr)
#pragma unroll
            for (int g = 0; g < 4; ++g) acc2[pr][g] = bias1d[g];

        gemm_acc<8>(acc2, g_H0 + (size_t)(1 - p) * Bsz * NH + bi * 64 * NH, NH, W1x,
                    A_s, W_s, tid, tx, ty, true);
        gemm_acc<8>(acc2, g_H1 + (size_t)p * Bsz * NH + bi * 64 * NH, NH, W1h,
                    A_s, W_s, tid, tx, ty, true);
#pragma unroll
        for (int pr = 0; pr < 4; ++pr) {
            float2 vi = unpack2(acc2[pr][0]);
            float2 vf = unpack2(acc2[pr][1]);
            float2 vg = unpack2(acc2[pr][2]);
            float2 vo = unpack2(acc2[pr][3]);
            float gi[2] = {vi.x, vi.y}, gf[2] = {vf.x, vf.y};
            float gg[2] = {vg.x, vg.y}, go[2] = {vo.x, vo.y};
#pragma unroll
            for (int h = 0; h < 2; ++h) {
                int e = 2 * pr + h;
                float c = fmaf(sigm(gf[h]), c1r[e], sigm(gi[h]) * tanhf(gg[h]));
                c1r[e] = c;
                g_H1[(size_t)(1 - p) * Bsz * NH + (b0 + e) * NH + jg] =
                    sigm(go[h]) * tanhf(c);
            }
        }
        group_barrier(bi);
        p ^= 1;
    }

    // ---------------- outputs ----------------
    float* outh = out + 2 * Bsz;
    float* outc = outh + 2 * Bsz * NH;
#pragma unroll
    for (int e = 0; e < 8; ++e) {
        int b = b0 + e;
        outh[b * NH + jg]            = g_H0[(size_t)p * Bsz * NH + b * NH + jg];
        outh[Bsz * NH + b * NH + jg] = g_H1[(size_t)p * Bsz * NH + b * NH + jg];
        outc[b * NH + jg]            = c0r[e];
        outc[Bsz * NH + b * NH + jg] = c1r[e];
    }

    // decoded head: only last timestep's layer1 h matters
    if (hi == 0 && tid < 64) {
        int b = bi * 64 + tid;
        const float* h1 = g_H1 + (size_t)p * Bsz * NH + b * NH;
        float d0 = decb[0], d1 = decb[1];
#pragma unroll 1
        for (int m = 0; m < 10; ++m) {
            float s = fcb[m];
            for (int j = 0; j < 256; ++j) s = fmaf(__ldcg(h1 + j), fcw[m * 256 + j], s);
            s = fmaxf(s, 0.f);
            d0 = fmaf(s, decw[m], d0);
            d1 = fmaf(s, decw[10 + m], d1);
        }
        out[b] = d0;
        out[Bsz + b] = d1;
    }
}

// -------------------- launch --------------------
extern "C" void kernel_launch(void* const* d_in, const int* in_sizes, int n_in,
                              void* d_out, int out_size) {
    const int*   input = (const int*)  d_in[0];
    const float* h0    = (const float*)d_in[1];
    const float* c0    = (const float*)d_in[2];
    const float* emb   = (const float*)d_in[3];
    const float* fcw   = (const float*)d_in[4];
    const float* fcb   = (const float*)d_in[5];
    const float* decw  = (const float*)d_in[6];
    const float* decb  = (const float*)d_in[7];
    const float* Wih0  = (const float*)d_in[8];
    const float* Whh0  = (const float*)d_in[9];
    const float* bih0  = (const float*)d_in[10];
    const float* bhh0  = (const float*)d_in[11];
    const float* Wih1  = (const float*)d_in[12];
    const float* Whh1  = (const float*)d_in[13];
    const float* bih1  = (const float*)d_in[14];
    const float* bhh1  = (const float*)d_in[15];
    float* out = (float*)d_out;

    long nX = (long)Tst * Bsz * KX;
    gather_emb_kernel<<<(unsigned)((nX + 255) / 256), 256>>>(input, emb);

    int nW = (KX + 3 * NH) * NG + 2 * NG;
    prep_weights_kernel<<<(nW + 255) / 256, 256>>>(Wih0, Whh0, bih0, bhh0,
                                                   Wih1, Whh1, bih1, bhh1);

    lstm_kernel<<<NCTA, 256>>>(h0, c0, fcw, fcb, decw, decb, out);
}

// round 5
// speedup vs baseline: 1.1862x; 1.0522x over previous
#include <cuda_runtime.h>

// ---------------------------------------------------------------------------
// RNNSent: 2-layer LSTM (T=300 steps after the .view trick), B=1024, NHID=256
// Round 3: packed fp32x2 FFMA2 mainloop (exact fp32, 2 FMA/issue) + K-tile 32.
// Outputs: decoded.T [2,1024] ++ h [2,1024,256] ++ c [2,1024,256]  (fp32)
// ---------------------------------------------------------------------------

#define Bsz   1024
#define Tst   300
#define NH    256
#define NG    1024        // 4*NH gate rows
#define KX    32          // padded layer0 input dim (25 -> 32)
#define GSIZE 8           // CTAs per batch-group (hidden split 256/32)
#define NGRP  16          // batch groups (1024/64)
#define NCTA  128

// -------------------- device scratch (static, no allocations) --------------
__device__ float g_X[(size_t)Tst * Bsz * KX];              // [t][b][kx] padded emb
// rows: [0,32)=Wih0T, [32,288)=Whh0T, [288,544)=Wih1T, [544,800)=Whh1T
// col' = hi*128 + g*32 + j  for gate row r = g*256 + hi*32 + j
__device__ float g_WT[(size_t)(KX + 3 * NH) * NG];
__device__ float g_bias[2 * NG];                            // permuted b_ih+b_hh
__device__ float g_H0[2 * Bsz * NH];                        // double-buffered h, layer0
__device__ float g_H1[2 * Bsz * NH];                        // layer1
__device__ unsigned g_bar_count[NGRP];
__device__ unsigned g_bar_gen[NGRP];

// -------------------- packed f32x2 helpers ----------------------------------
__device__ __forceinline__ unsigned long long dup2(float w) {
    unsigned long long r;
    asm("mov.b64 %0, {%1, %1};" : "=l"(r) : "f"(w));
    return r;
}
__device__ __forceinline__ void ffma2(unsigned long long& d, unsigned long long a,
                                      unsigned long long b) {
    asm("fma.rn.f32x2 %0, %1, %2, %0;" : "+l"(d) : "l"(a), "l"(b));
}
__device__ __forceinline__ float2 unpack2(unsigned long long v) {
    float2 f;
    asm("mov.b64 {%0, %1}, %2;" : "=f"(f.x), "=f"(f.y) : "l"(v));
    return f;
}

// -------------------- kernel 1: embedding gather + pad ---------------------
__global__ void gather_emb_kernel(const int* __restrict__ input,
                                  const float* __restrict__ emb) {
    long idx = (long)blockIdx.x * blockDim.x + threadIdx.x;
    long total = (long)Tst * Bsz * KX;
    if (idx >= total) return;
    int k = (int)(idx & (KX - 1));
    long tb = idx >> 5;
    int b = (int)(tb & (Bsz - 1));
    int t = (int)(tb >> 10);
    float v = 0.f;
    if (k < 25) {
        long flat = (long)t * (Bsz * 25) + b * 25 + k;
        int s  = (int)(flat / (Bsz * 300));
        int rr = (int)(flat % (Bsz * 300));
        int bb = rr / 300;
        int e  = rr % 300;
        int tok = input[bb * 25 + s];
        v = emb[(long)tok * 300 + e];
    }
    g_X[idx] = v;
}

// -------------------- kernel 2: weight transpose + permute -----------------
__global__ void prep_weights_kernel(
    const float* __restrict__ Wih0, const float* __restrict__ Whh0,
    const float* __restrict__ bih0, const float* __restrict__ bhh0,
    const float* __restrict__ Wih1, const float* __restrict__ Whh1,
    const float* __restrict__ bih1, const float* __restrict__ bhh1) {
    int idx = blockIdx.x * blockDim.x + threadIdx.x;
    const int total = (KX + 3 * NH) * NG;   // 819200
    if (idx < total) {
        int row  = idx >> 10;
        int colp = idx & 1023;
        int hi = colp >> 7, g = (colp >> 5) & 3, j = colp & 31;
        int r = g * 256 + hi * 32 + j;      // original gate row
        float v;
        if (row < KX)               { int k = row;               v = (k < 25) ? Wih0[r * 25 + k] : 0.f; }
        else if (row < KX + NH)     { int k = row - KX;          v = Whh0[r * 256 + k]; }
        else if (row < KX + 2 * NH) { int k = row - (KX + NH);   v = Wih1[r * 256 + k]; }
        else                        { int k = row - (KX + 2*NH); v = Whh1[r * 256 + k]; }
        g_WT[idx] = v;
    } else if (idx < total + 2 * NG) {
        int i2 = idx - total;
        int l = i2 >> 10, colp = i2 & 1023;
        int hi = colp >> 7, g = (colp >> 5) & 3, j = colp & 31;
        int r = g * 256 + hi * 32 + j;
        g_bias[i2] = (l == 0) ? (bih0[r] + bhh0[r]) : (bih1[r] + bhh1[r]);
    }
}

// -------------------- group barrier (8 co-resident CTAs) -------------------
__device__ __forceinline__ void group_barrier(int grp) {
    __syncthreads();
    if (threadIdx.x == 0) {
        __threadfence();   // release: make this CTA's h writes visible
        volatile unsigned* genp = &g_bar_gen[grp];
        unsigned gen = *genp;
        unsigned old = atomicAdd(&g_bar_count[grp], 1u);
        if (old == GSIZE - 1) {
            ((volatile unsigned*)&g_bar_count[grp])[0] = 0u;
            __threadfence();
            atomicExch(&g_bar_gen[grp], gen + 1u);
        } else {
            while (*genp == gen) { __nanosleep(64); }
        }
        __threadfence();   // acquire
    }
    __syncthreads();
}

// -------------------- fp32x2 register-tiled GEMM fragment ------------------
// CTA computes G[64 batch, 128 gatecols], K-tile = 32.
// Thread (ty in [0,8), tx in [0,32)): 8 batch rows (as 4 f32x2 pairs) x 4 gates.
struct Frag {
    float4 a0, a1;                 // A: (b, kq*4..) and (b, 16+kq*4..)
    float4 w00, w01, w10, w11;     // W rows kk, kk+16; col halves 0 / +64
};

__device__ __forceinline__ void load_frag(const float* __restrict__ Ag, int lda,
                                          const float* __restrict__ Wrow, int kc,
                                          int tid, bool a_cg, Frag& f) {
    int b = tid >> 2, q = tid & 3;
    const float4* ap0 = (const float4*)(Ag + (size_t)b * lda + kc + q * 4);
    const float4* ap1 = (const float4*)(Ag + (size_t)b * lda + kc + 16 + q * 4);
    f.a0 = a_cg ? __ldcg(ap0) : *ap0;
    f.a1 = a_cg ? __ldcg(ap1) : *ap1;
    int kk = tid >> 4, c = tid & 15;
    const float* wp0 = Wrow + (size_t)(kc + kk) * NG;
    const float* wp1 = Wrow + (size_t)(kc + kk + 16) * NG;
    f.w00 = *(const float4*)(wp0 + 4 * c);
    f.w01 = *(const float4*)(wp0 + 4 * c + 64);
    f.w10 = *(const float4*)(wp1 + 4 * c);
    f.w11 = *(const float4*)(wp1 + 4 * c + 64);
}

__device__ __forceinline__ void store_frag(float (&A_s)[32][68], float (&W_s)[32][128],
                                           int tid, const Frag& f) {
    int b = tid >> 2, q = tid & 3;
    A_s[q * 4 + 0][b] = f.a0.x; A_s[q * 4 + 1][b] = f.a0.y;
    A_s[q * 4 + 2][b] = f.a0.z; A_s[q * 4 + 3][b] = f.a0.w;
    A_s[16 + q * 4 + 0][b] = f.a1.x; A_s[16 + q * 4 + 1][b] = f.a1.y;
    A_s[16 + q * 4 + 2][b] = f.a1.z; A_s[16 + q * 4 + 3][b] = f.a1.w;
    int kk = tid >> 4, c = tid & 15;
    *(float4*)&W_s[kk][4 * c]           = f.w00;
    *(float4*)&W_s[kk][4 * c + 64]      = f.w01;
    *(float4*)&W_s[kk + 16][4 * c]      = f.w10;
    *(float4*)&W_s[kk + 16][4 * c + 64] = f.w11;
}

template <int KT>   // KT in units of 32-k tiles
__device__ __forceinline__ void gemm_acc(unsigned long long (&acc2)[4][4],
                                         const float* __restrict__ Ag, int lda,
                                         const float* __restrict__ Wrow,
                                         float (&A_s)[32][68], float (&W_s)[32][128],
                                         int tid, int tx, int ty, bool a_cg) {
    Frag f;
    load_frag(Ag, lda, Wrow, 0, tid, a_cg, f);
#pragma unroll 1
    for (int kt = 0; kt < KT; ++kt) {
        __syncthreads();
        store_frag(A_s, W_s, tid, f);
        __syncthreads();
        if (kt + 1 < KT) load_frag(Ag, lda, Wrow, (kt + 1) * 32, tid, a_cg, f);
#pragma unroll
        for (int kk = 0; kk < 32; ++kk) {
            const ulonglong2* ap = (const ulonglong2*)&A_s[kk][ty * 8];
            ulonglong2 aA = ap[0];   // pairs (e0,e1), (e2,e3)
            ulonglong2 aB = ap[1];   // pairs (e4,e5), (e6,e7)
            unsigned long long w0 = dup2(W_s[kk][tx]);
            unsigned long long w1 = dup2(W_s[kk][32 + tx]);
            unsigned long long w2 = dup2(W_s[kk][64 + tx]);
            unsigned long long w3 = dup2(W_s[kk][96 + tx]);
            ffma2(acc2[0][0], aA.x, w0); ffma2(acc2[0][1], aA.x, w1);
            ffma2(acc2[0][2], aA.x, w2); ffma2(acc2[0][3], aA.x, w3);
            ffma2(acc2[1][0], aA.y, w0); ffma2(acc2[1][1], aA.y, w1);
            ffma2(acc2[1][2], aA.y, w2); ffma2(acc2[1][3], aA.y, w3);
            ffma2(acc2[2][0], aB.x, w0); ffma2(acc2[2][1], aB.x, w1);
            ffma2(acc2[2][2], aB.x, w2); ffma2(acc2[2][3], aB.x, w3);
            ffma2(acc2[3][0], aB.y, w0); ffma2(acc2[3][1], aB.y, w1);
            ffma2(acc2[3][2], aB.y, w2); ffma2(acc2[3][3], aB.y, w3);
        }
    }
}

__device__ __forceinline__ float sigm(float x) { return 1.f / (1.f + expf(-x)); }

// -------------------- kernel 3: persistent fused 2-layer LSTM --------------
__global__ void __launch_bounds__(256, 1) lstm_kernel(
    const float* __restrict__ h0in, const float* __restrict__ c0in,
    const float* __restrict__ fcw, const float* __restrict__ fcb,
    const float* __restrict__ decw, const float* __restrict__ decb,
    float* __restrict__ out) {
    __shared__ __align__(16) float A_s[32][68];
    __shared__ __align__(16) float W_s[32][128];

    const int tid = threadIdx.x;
    const int tx = tid & 31, ty = tid >> 5;
    const int bi = blockIdx.x >> 3;   // batch group 0..15
    const int hi = blockIdx.x & 7;    // hidden slice 0..7
    const int jg = hi * 32 + tx;      // global hidden index owned by this thread
    const int b0 = bi * 64 + ty * 8;  // first batch row of this thread

    unsigned long long bias0d[4], bias1d[4];
#pragma unroll
    for (int g = 0; g < 4; ++g) {
        bias0d[g] = dup2(g_bias[hi * 128 + g * 32 + tx]);
        bias1d[g] = dup2(g_bias[NG + hi * 128 + g * 32 + tx]);
    }

    float c0r[8], c1r[8];
#pragma unroll
    for (int e = 0; e < 8; ++e) {
        int b = b0 + e;
        c0r[e] = c0in[b * NH + jg];
        c1r[e] = c0in[Bsz * NH + b * NH + jg];
        g_H0[b * NH + jg] = h0in[b * NH + jg];
        g_H1[b * NH + jg] = h0in[Bsz * NH + b * NH + jg];
    }
    group_barrier(bi);

    const float* W0x = g_WT + hi * 128;
    const float* W0h = g_WT + (size_t)KX * NG + hi * 128;
    const float* W1x = g_WT + (size_t)(KX + NH) * NG + hi * 128;
    const float* W1h = g_WT + (size_t)(KX + 2 * NH) * NG + hi * 128;

    int p = 0;
    for (int t = 0; t < Tst; ++t) {
        // ---------------- layer 0 ----------------
        unsigned long long acc2[4][4];
#pragma unroll
        for (int pr = 0; pr < 4; ++pr)
#pragma unroll
            for (int g = 0; g < 4; ++g) acc2[pr][g] = bias0d[g];

        gemm_acc<1>(acc2, g_X + ((size_t)t * Bsz + bi * 64) * KX, KX, W0x,
                    A_s, W_s, tid, tx, ty, false);
        gemm_acc<8>(acc2, g_H0 + (size_t)p * Bsz * NH + bi * 64 * NH, NH, W0h,
                    A_s, W_s, tid, tx, ty, true);
#pragma unroll
        for (int pr = 0; pr < 4; ++pr) {
            float2 vi = unpack2(acc2[pr][0]);
            float2 vf = unpack2(acc2[pr][1]);
            float2 vg = unpack2(acc2[pr][2]);
            float2 vo = unpack2(acc2[pr][3]);
            float gi[2] = {vi.x, vi.y}, gf[2] = {vf.x, vf.y};
            float gg[2] = {vg.x, vg.y}, go[2] = {vo.x, vo.y};
#pragma unroll
            for (int h = 0; h < 2; ++h) {
                int e = 2 * pr + h;
                float c = fmaf(sigm(gf[h]), c0r[e], sigm(gi[h]) * tanhf(gg[h]));
                c0r[e] = c;
                g_H0[(size_t)(1 - p) * Bsz * NH + (b0 + e) * NH + jg] =
                    sigm(go[h]) * tanhf(c);
            }
        }
        group_barrier(bi);

        // ---------------- layer 1 ----------------
#pragma unroll
        for (int pr = 0; pr < 4; ++pr)
#pragma unroll
            for (int g = 0; g < 4; ++g) acc2[pr][g] = bias1d[g];

        gemm_acc<8>(acc2, g_H0 + (size_t)(1 - p) * Bsz * NH + bi * 64 * NH, NH, W1x,
                    A_s, W_s, tid, tx, ty, true);
        gemm_acc<8>(acc2, g_H1 + (size_t)p * Bsz * NH + bi * 64 * NH, NH, W1h,
                    A_s, W_s, tid, tx, ty, true);
#pragma unroll
        for (int pr = 0; pr < 4; ++pr) {
            float2 vi = unpack2(acc2[pr][0]);
            float2 vf = unpack2(acc2[pr][1]);
            float2 vg = unpack2(acc2[pr][2]);
            float2 vo = unpack2(acc2[pr][3]);
            float gi[2] = {vi.x, vi.y}, gf[2] = {vf.x, vf.y};
            float gg[2] = {vg.x, vg.y}, go[2] = {vo.x, vo.y};
#pragma unroll
            for (int h = 0; h < 2; ++h) {
                int e = 2 * pr + h;
                float c = fmaf(sigm(gf[h]), c1r[e], sigm(gi[h]) * tanhf(gg[h]));
                c1r[e] = c;
                g_H1[(size_t)(1 - p) * Bsz * NH + (b0 + e) * NH + jg] =
                    sigm(go[h]) * tanhf(c);
            }
        }
        group_barrier(bi);
        p ^= 1;
    }

    // ---------------- outputs ----------------
    float* outh = out + 2 * Bsz;
    float* outc = outh + 2 * Bsz * NH;
#pragma unroll
    for (int e = 0; e < 8; ++e) {
        int b = b0 + e;
        outh[b * NH + jg]            = g_H0[(size_t)p * Bsz * NH + b * NH + jg];
        outh[Bsz * NH + b * NH + jg] = g_H1[(size_t)p * Bsz * NH + b * NH + jg];
        outc[b * NH + jg]            = c0r[e];
        outc[Bsz * NH + b * NH + jg] = c1r[e];
    }

    // decoded head: only last timestep's layer1 h matters
    if (hi == 0 && tid < 64) {
        int b = bi * 64 + tid;
        const float* h1 = g_H1 + (size_t)p * Bsz * NH + b * NH;
        float d0 = decb[0], d1 = decb[1];
#pragma unroll 1
        for (int m = 0; m < 10; ++m) {
            float s = fcb[m];
            for (int j = 0; j < 256; ++j) s = fmaf(__ldcg(h1 + j), fcw[m * 256 + j], s);
            s = fmaxf(s, 0.f);
            d0 = fmaf(s, decw[m], d0);
            d1 = fmaf(s, decw[10 + m], d1);
        }
        out[b] = d0;
        out[Bsz + b] = d1;
    }
}

// -------------------- launch --------------------
extern "C" void kernel_launch(void* const* d_in, const int* in_sizes, int n_in,
                              void* d_out, int out_size) {
    const int*   input = (const int*)  d_in[0];
    const float* h0    = (const float*)d_in[1];
    const float* c0    = (const float*)d_in[2];
    const float* emb   = (const float*)d_in[3];
    const float* fcw   = (const float*)d_in[4];
    const float* fcb   = (const float*)d_in[5];
    const float* decw  = (const float*)d_in[6];
    const float* decb  = (const float*)d_in[7];
    const float* Wih0  = (const float*)d_in[8];
    const float* Whh0  = (const float*)d_in[9];
    const float* bih0  = (const float*)d_in[10];
    const float* bhh0  = (const float*)d_in[11];
    const float* Wih1  = (const float*)d_in[12];
    const float* Whh1  = (const float*)d_in[13];
    const float* bih1  = (const float*)d_in[14];
    const float* bhh1  = (const float*)d_in[15];
    float* out = (float*)d_out;

    long nX = (long)Tst * Bsz * KX;
    gather_emb_kernel<<<(unsigned)((nX + 255) / 256), 256>>>(input, emb);

    int nW = (KX + 3 * NH) * NG + 2 * NG;
    prep_weights_kernel<<<(nW + 255) / 256, 256>>>(Wih0, Whh0, bih0, bhh0,
                                                   Wih1, Whh1, bih1, bhh1);

    lstm_kernel<<<NCTA, 256>>>(h0, c0, fcw, fcb, decw, decb, out);
}

// round 6
// speedup vs baseline: 1.1886x; 1.0021x over previous
#include <cuda_runtime.h>

// ---------------------------------------------------------------------------
// RNNSent: 2-layer LSTM (T=300 steps after the .view trick), B=1024, NHID=256
// Round 3: packed fp32x2 FFMA2 mainloop (exact fp32, 2 FMA/issue) + K-tile 32.
// Outputs: decoded.T [2,1024] ++ h [2,1024,256] ++ c [2,1024,256]  (fp32)
// ---------------------------------------------------------------------------

#define Bsz   1024
#define Tst   300
#define NH    256
#define NG    1024        // 4*NH gate rows
#define KX    32          // padded layer0 input dim (25 -> 32)
#define GSIZE 8           // CTAs per batch-group (hidden split 256/32)
#define NGRP  16          // batch groups (1024/64)
#define NCTA  128

// -------------------- device scratch (static, no allocations) --------------
__device__ float g_X[(size_t)Tst * Bsz * KX];              // [t][b][kx] padded emb
// rows: [0,32)=Wih0T, [32,288)=Whh0T, [288,544)=Wih1T, [544,800)=Whh1T
// col' = hi*128 + g*32 + j  for gate row r = g*256 + hi*32 + j
__device__ float g_WT[(size_t)(KX + 3 * NH) * NG];
__device__ float g_bias[2 * NG];                            // permuted b_ih+b_hh
__device__ float g_H0[2 * Bsz * NH];                        // double-buffered h, layer0
__device__ float g_H1[2 * Bsz * NH];                        // layer1
__device__ unsigned g_bar_count[NGRP];
__device__ unsigned g_bar_gen[NGRP];

// -------------------- packed f32x2 helpers ----------------------------------
__device__ __forceinline__ unsigned long long dup2(float w) {
    unsigned long long r;
    asm("mov.b64 %0, {%1, %1};" : "=l"(r) : "f"(w));
    return r;
}
__device__ __forceinline__ void ffma2(unsigned long long& d, unsigned long long a,
                                      unsigned long long b) {
    asm("fma.rn.f32x2 %0, %1, %2, %0;" : "+l"(d) : "l"(a), "l"(b));
}
__device__ __forceinline__ float2 unpack2(unsigned long long v) {
    float2 f;
    asm("mov.b64 {%0, %1}, %2;" : "=f"(f.x), "=f"(f.y) : "l"(v));
    return f;
}

// -------------------- kernel 1: embedding gather + pad ---------------------
__global__ void gather_emb_kernel(const int* __restrict__ input,
                                  const float* __restrict__ emb) {
    long idx = (long)blockIdx.x * blockDim.x + threadIdx.x;
    long total = (long)Tst * Bsz * KX;
    if (idx >= total) return;
    int k = (int)(idx & (KX - 1));
    long tb = idx >> 5;
    int b = (int)(tb & (Bsz - 1));
    int t = (int)(tb >> 10);
    float v = 0.f;
    if (k < 25) {
        long flat = (long)t * (Bsz * 25) + b * 25 + k;
        int s  = (int)(flat / (Bsz * 300));
        int rr = (int)(flat % (Bsz * 300));
        int bb = rr / 300;
        int e  = rr % 300;
        int tok = input[bb * 25 + s];
        v = emb[(long)tok * 300 + e];
    }
    g_X[idx] = v;
}

// -------------------- kernel 2: weight transpose + permute -----------------
__global__ void prep_weights_kernel(
    const float* __restrict__ Wih0, const float* __restrict__ Whh0,
    const float* __restrict__ bih0, const float* __restrict__ bhh0,
    const float* __restrict__ Wih1, const float* __restrict__ Whh1,
    const float* __restrict__ bih1, const float* __restrict__ bhh1) {
    int idx = blockIdx.x * blockDim.x + threadIdx.x;
    const int total = (KX + 3 * NH) * NG;   // 819200
    if (idx < total) {
        int row  = idx >> 10;
        int colp = idx & 1023;
        int hi = colp >> 7, g = (colp >> 5) & 3, j = colp & 31;
        int r = g * 256 + hi * 32 + j;      // original gate row
        float v;
        if (row < KX)               { int k = row;               v = (k < 25) ? Wih0[r * 25 + k] : 0.f; }
        else if (row < KX + NH)     { int k = row - KX;          v = Whh0[r * 256 + k]; }
        else if (row < KX + 2 * NH) { int k = row - (KX + NH);   v = Wih1[r * 256 + k]; }
        else                        { int k = row - (KX + 2*NH); v = Whh1[r * 256 + k]; }
        g_WT[idx] = v;
    } else if (idx < total + 2 * NG) {
        int i2 = idx - total;
        int l = i2 >> 10, colp = i2 & 1023;
        int hi = colp >> 7, g = (colp >> 5) & 3, j = colp & 31;
        int r = g * 256 + hi * 32 + j;
        g_bias[i2] = (l == 0) ? (bih0[r] + bhh0[r]) : (bih1[r] + bhh1[r]);
    }
}

// -------------------- group barrier (8 co-resident CTAs) -------------------
__device__ __forceinline__ void group_barrier(int grp) {
    __syncthreads();
    if (threadIdx.x == 0) {
        __threadfence();   // release: make this CTA's h writes visible
        volatile unsigned* genp = &g_bar_gen[grp];
        unsigned gen = *genp;
        unsigned old = atomicAdd(&g_bar_count[grp], 1u);
        if (old == GSIZE - 1) {
            ((volatile unsigned*)&g_bar_count[grp])[0] = 0u;
            __threadfence();
            atomicExch(&g_bar_gen[grp], gen + 1u);
        } else {
            while (*genp == gen) { __nanosleep(64); }
        }
        __threadfence();   // acquire
    }
    __syncthreads();
}

// -------------------- fp32x2 register-tiled GEMM fragment ------------------
// CTA computes G[64 batch, 128 gatecols], K-tile = 32.
// Thread (ty in [0,8), tx in [0,32)): 8 batch rows (as 4 f32x2 pairs) x 4 gates.
struct Frag {
    float4 a0, a1;                 // A: (b, kq*4..) and (b, 16+kq*4..)
    float4 w00, w01, w10, w11;     // W rows kk, kk+16; col halves 0 / +64
};

__device__ __forceinline__ void load_frag(const float* __restrict__ Ag, int lda,
                                          const float* __restrict__ Wrow, int kc,
                                          int tid, bool a_cg, Frag& f) {
    int b = tid >> 2, q = tid & 3;
    const float4* ap0 = (const float4*)(Ag + (size_t)b * lda + kc + q * 4);
    const float4* ap1 = (const float4*)(Ag + (size_t)b * lda + kc + 16 + q * 4);
    f.a0 = a_cg ? __ldcg(ap0) : *ap0;
    f.a1 = a_cg ? __ldcg(ap1) : *ap1;
    int kk = tid >> 4, c = tid & 15;
    const float* wp0 = Wrow + (size_t)(kc + kk) * NG;
    const float* wp1 = Wrow + (size_t)(kc + kk + 16) * NG;
    f.w00 = *(const float4*)(wp0 + 4 * c);
    f.w01 = *(const float4*)(wp0 + 4 * c + 64);
    f.w10 = *(const float4*)(wp1 + 4 * c);
    f.w11 = *(const float4*)(wp1 + 4 * c + 64);
}

__device__ __forceinline__ void store_frag(float (&A_s)[32][68], float (&W_s)[32][128],
                                           int tid, const Frag& f) {
    int b = tid >> 2, q = tid & 3;
    A_s[q * 4 + 0][b] = f.a0.x; A_s[q * 4 + 1][b] = f.a0.y;
    A_s[q * 4 + 2][b] = f.a0.z; A_s[q * 4 + 3][b] = f.a0.w;
    A_s[16 + q * 4 + 0][b] = f.a1.x; A_s[16 + q * 4 + 1][b] = f.a1.y;
    A_s[16 + q * 4 + 2][b] = f.a1.z; A_s[16 + q * 4 + 3][b] = f.a1.w;
    int kk = tid >> 4, c = tid & 15;
    *(float4*)&W_s[kk][4 * c]           = f.w00;
    *(float4*)&W_s[kk][4 * c + 64]      = f.w01;
    *(float4*)&W_s[kk + 16][4 * c]      = f.w10;
    *(float4*)&W_s[kk + 16][4 * c + 64] = f.w11;
}

template <int KT>   // KT in units of 32-k tiles
__device__ __forceinline__ void gemm_acc(unsigned long long (&acc2)[4][4],
                                         const float* __restrict__ Ag, int lda,
                                         const float* __restrict__ Wrow,
                                         float (&A_s)[32][68], float (&W_s)[32][128],
                                         int tid, int tx, int ty, bool a_cg) {
    Frag f;
    load_frag(Ag, lda, Wrow, 0, tid, a_cg, f);
#pragma unroll 1
    for (int kt = 0; kt < KT; ++kt) {
        __syncthreads();
        store_frag(A_s, W_s, tid, f);
        __syncthreads();
        if (kt + 1 < KT) load_frag(Ag, lda, Wrow, (kt + 1) * 32, tid, a_cg, f);
#pragma unroll
        for (int kk = 0; kk < 32; ++kk) {
            const ulonglong2* ap = (const ulonglong2*)&A_s[kk][ty * 8];
            ulonglong2 aA = ap[0];   // pairs (e0,e1), (e2,e3)
            ulonglong2 aB = ap[1];   // pairs (e4,e5), (e6,e7)
            unsigned long long w0 = dup2(W_s[kk][tx]);
            unsigned long long w1 = dup2(W_s[kk][32 + tx]);
            unsigned long long w2 = dup2(W_s[kk][64 + tx]);
            unsigned long long w3 = dup2(W_s[kk][96 + tx]);
            ffma2(acc2[0][0], aA.x, w0); ffma2(acc2[0][1], aA.x, w1);
            ffma2(acc2[0][2], aA.x, w2); ffma2(acc2[0][3], aA.x, w3);
            ffma2(acc2[1][0], aA.y, w0); ffma2(acc2[1][1], aA.y, w1);
            ffma2(acc2[1][2], aA.y, w2); ffma2(acc2[1][3], aA.y, w3);
            ffma2(acc2[2][0], aB.x, w0); ffma2(acc2[2][1], aB.x, w1);
            ffma2(acc2[2][2], aB.x, w2); ffma2(acc2[2][3], aB.x, w3);
            ffma2(acc2[3][0], aB.y, w0); ffma2(acc2[3][1], aB.y, w1);
            ffma2(acc2[3][2], aB.y, w2); ffma2(acc2[3][3], aB.y, w3);
        }
    }
}

__device__ __forceinline__ float sigm(float x) { return 1.f / (1.f + expf(-x)); }

// -------------------- kernel 3: persistent fused 2-layer LSTM --------------
__global__ void __launch_bounds__(256, 1) lstm_kernel(
    const float* __restrict__ h0in, const float* __restrict__ c0in,
    const float* __restrict__ fcw, const float* __restrict__ fcb,
    const float* __restrict__ decw, const float* __restrict__ decb,
    float* __restrict__ out) {
    __shared__ __align__(16) float A_s[32][68];
    __shared__ __align__(16) float W_s[32][128];

    const int tid = threadIdx.x;
    const int tx = tid & 31, ty = tid >> 5;
    const int bi = blockIdx.x >> 3;   // batch group 0..15
    const int hi = blockIdx.x & 7;    // hidden slice 0..7
    const int jg = hi * 32 + tx;      // global hidden index owned by this thread
    const int b0 = bi * 64 + ty * 8;  // first batch row of this thread

    unsigned long long bias0d[4], bias1d[4];
#pragma unroll
    for (int g = 0; g < 4; ++g) {
        bias0d[g] = dup2(g_bias[hi * 128 + g * 32 + tx]);
        bias1d[g] = dup2(g_bias[NG + hi * 128 + g * 32 + tx]);
    }

    float c0r[8], c1r[8];
#pragma unroll
    for (int e = 0; e < 8; ++e) {
        int b = b0 + e;
        c0r[e] = c0in[b * NH + jg];
        c1r[e] = c0in[Bsz * NH + b * NH + jg];
        g_H0[b * NH + jg] = h0in[b * NH + jg];
        g_H1[b * NH + jg] = h0in[Bsz * NH + b * NH + jg];
    }
    group_barrier(bi);

    const float* W0x = g_WT + hi * 128;
    const float* W0h = g_WT + (size_t)KX * NG + hi * 128;
    const float* W1x = g_WT + (size_t)(KX + NH) * NG + hi * 128;
    const float* W1h = g_WT + (size_t)(KX + 2 * NH) * NG + hi * 128;

    int p = 0;
    for (int t = 0; t < Tst; ++t) {
        // ---------------- layer 0 ----------------
        unsigned long long acc2[4][4];
#pragma unroll
        for (int pr = 0; pr < 4; ++pr)
#pragma unroll
            for (int g = 0; g < 4; ++g) acc2[pr][g] = bias0d[g];

        gemm_acc<1>(acc2, g_X + ((size_t)t * Bsz + bi * 64) * KX, KX, W0x,
                    A_s, W_s, tid, tx, ty, false);
        gemm_acc<8>(acc2, g_H0 + (size_t)p * Bsz * NH + bi * 64 * NH, NH, W0h,
                    A_s, W_s, tid, tx, ty, true);
#pragma unroll
        for (int pr = 0; pr < 4; ++pr) {
            float2 vi = unpack2(acc2[pr][0]);
            float2 vf = unpack2(acc2[pr][1]);
            float2 vg = unpack2(acc2[pr][2]);
            float2 vo = unpack2(acc2[pr][3]);
            float gi[2] = {vi.x, vi.y}, gf[2] = {vf.x, vf.y};
            float gg[2] = {vg.x, vg.y}, go[2] = {vo.x, vo.y};
#pragma unroll
            for (int h = 0; h < 2; ++h) {
                int e = 2 * pr + h;
                float c = fmaf(sigm(gf[h]), c0r[e], sigm(gi[h]) * tanhf(gg[h]));
                c0r[e] = c;
                g_H0[(size_t)(1 - p) * Bsz * NH + (b0 + e) * NH + jg] =
                    sigm(go[h]) * tanhf(c);
            }
        }
        group_barrier(bi);

        // ---------------- layer 1 ----------------
#pragma unroll
        for (int pr = 0; pr < 4; ++pr)
#pragma unroll
            for (int g = 0; g < 4; ++g) acc2[pr][g] = bias1d[g];

        gemm_acc<8>(acc2, g_H0 + (size_t)(1 - p) * Bsz * NH + bi * 64 * NH, NH, W1x,
                    A_s, W_s, tid, tx, ty, true);
        gemm_acc<8>(acc2, g_H1 + (size_t)p * Bsz * NH + bi * 64 * NH, NH, W1h,
                    A_s, W_s, tid, tx, ty, true);
#pragma unroll
        for (int pr = 0; pr < 4; ++pr) {
            float2 vi = unpack2(acc2[pr][0]);
            float2 vf = unpack2(acc2[pr][1]);
            float2 vg = unpack2(acc2[pr][2]);
            float2 vo = unpack2(acc2[pr][3]);
            float gi[2] = {vi.x, vi.y}, gf[2] = {vf.x, vf.y};
            float gg[2] = {vg.x, vg.y}, go[2] = {vo.x, vo.y};
#pragma unroll
            for (int h = 0; h < 2; ++h) {
                int e = 2 * pr + h;
                float c = fmaf(sigm(gf[h]), c1r[e], sigm(gi[h]) * tanhf(gg[h]));
                c1r[e] = c;
                g_H1[(size_t)(1 - p) * Bsz * NH + (b0 + e) * NH + jg] =
                    sigm(go[h]) * tanhf(c);
            }
        }
        group_barrier(bi);
        p ^= 1;
    }

    // ---------------- outputs ----------------
    float* outh = out + 2 * Bsz;
    float* outc = outh + 2 * Bsz * NH;
#pragma unroll
    for (int e = 0; e < 8; ++e) {
        int b = b0 + e;
        outh[b * NH + jg]            = g_H0[(size_t)p * Bsz * NH + b * NH + jg];
        outh[Bsz * NH + b * NH + jg] = g_H1[(size_t)p * Bsz * NH + b * NH + jg];
        outc[b * NH + jg]            = c0r[e];
        outc[Bsz * NH + b * NH + jg] = c1r[e];
    }

    // decoded head: only last timestep's layer1 h matters
    if (hi == 0 && tid < 64) {
        int b = bi * 64 + tid;
        const float* h1 = g_H1 + (size_t)p * Bsz * NH + b * NH;
        float d0 = decb[0], d1 = decb[1];
#pragma unroll 1
        for (int m = 0; m < 10; ++m) {
            float s = fcb[m];
            for (int j = 0; j < 256; ++j) s = fmaf(__ldcg(h1 + j), fcw[m * 256 + j], s);
            s = fmaxf(s, 0.f);
            d0 = fmaf(s, decw[m], d0);
            d1 = fmaf(s, decw[10 + m], d1);
        }
        out[b] = d0;
        out[Bsz + b] = d1;
    }
}

// -------------------- launch --------------------
extern "C" void kernel_launch(void* const* d_in, const int* in_sizes, int n_in,
                              void* d_out, int out_size) {
    const int*   input = (const int*)  d_in[0];
    const float* h0    = (const float*)d_in[1];
    const float* c0    = (const float*)d_in[2];
    const float* emb   = (const float*)d_in[3];
    const float* fcw   = (const float*)d_in[4];
    const float* fcb   = (const float*)d_in[5];
    const float* decw  = (const float*)d_in[6];
    const float* decb  = (const float*)d_in[7];
    const float* Wih0  = (const float*)d_in[8];
    const float* Whh0  = (const float*)d_in[9];
    const float* bih0  = (const float*)d_in[10];
    const float* bhh0  = (const float*)d_in[11];
    const float* Wih1  = (const float*)d_in[12];
    const float* Whh1  = (const float*)d_in[13];
    const float* bih1  = (const float*)d_in[14];
    const float* bhh1  = (const float*)d_in[15];
    float* out = (float*)d_out;

    long nX = (long)Tst * Bsz * KX;
    gather_emb_kernel<<<(unsigned)((nX + 255) / 256), 256>>>(input, emb);

    int nW = (KX + 3 * NH) * NG + 2 * NG;
    prep_weights_kernel<<<(nW + 255) / 256, 256>>>(Wih0, Whh0, bih0, bhh0,
                                                   Wih1, Whh1, bih1, bhh1);

    lstm_kernel<<<NCTA, 256>>>(h0, c0, fcw, fcb, decw, decb, out);
}